// round 9
// baseline (speedup 1.0000x reference)
#include <cuda_runtime.h>
#include <cuda_fp16.h>
#include <math.h>

#define BS   8
#define T_   32
#define C_   64
#define NN   4096
#define KK   32
#define DD   64
#define HH   64
#define FIN  320   // 5*D

// ---------------- persistent scratch (no allocation allowed) ----------------
__device__ __half g_pmh[2][BS * NN * DD];  // double-buffered messages (fp16)
__device__ float  g_h [BS * NN * DD];      // hidden state (fp32, in-place)
__device__ float  g_ep[BS * NN * DD];      // eff_prim
__device__ float  g_ek[BS * NN * DD];      // eff_key
__device__ float  g_ed[BS * NN];           // eff_decay (scalar per b,n)

// fast sigmoid
__device__ __forceinline__ float sigf(float x) {
    return __fdividef(1.f, 1.f + __expf(-x));
}
// fast tanh: 1 - 2/(e^{2x}+1).  Saturates correctly at +/-inf.
__device__ __forceinline__ float tanhfast(float x) {
    const float e = __expf(2.f * x);
    return 1.f - __fdividef(2.f, e + 1.f);
}

// ---- packed f32x2 helpers (Blackwell) ----
typedef unsigned long long u64;
__device__ __forceinline__ u64 pk2(float lo, float hi) {
    u64 r;
    asm("mov.b64 %0, {%1, %2};" : "=l"(r) : "f"(lo), "f"(hi));
    return r;
}
__device__ __forceinline__ float2 upk2(u64 v) {
    float2 r;
    asm("mov.b64 {%0, %1}, %2;" : "=f"(r.x), "=f"(r.y) : "l"(v));
    return r;
}
__device__ __forceinline__ u64 mul2(u64 a, u64 b) {
    u64 r;
    asm("mul.rn.f32x2 %0, %1, %2;" : "=l"(r) : "l"(a), "l"(b));
    return r;
}
__device__ __forceinline__ u64 fma2(u64 a, u64 b, u64 c) {
    u64 r;
    asm("fma.rn.f32x2 %0, %1, %2, %3;" : "=l"(r) : "l"(a), "l"(b), "l"(c));
    return r;
}

// butterfly multi-reduce: 8 sums over 32 lanes; lane l ends with sum for
// kk = (l>>2)&7
__device__ __forceinline__ float multireduce8(float v[8], int l) {
    const bool h16 = (l & 16);
    #pragma unroll
    for (int i = 0; i < 4; i++) {
        const float keep = h16 ? v[4 + i] : v[i];
        const float send = h16 ? v[i]     : v[4 + i];
        v[i] = keep + __shfl_xor_sync(0xffffffffu, send, 16);
    }
    const bool h8 = (l & 8);
    #pragma unroll
    for (int i = 0; i < 2; i++) {
        const float keep = h8 ? v[2 + i] : v[i];
        const float send = h8 ? v[i]     : v[2 + i];
        v[i] = keep + __shfl_xor_sync(0xffffffffu, send, 8);
    }
    const bool h4 = (l & 4);
    {
        const float keep = h4 ? v[1] : v[0];
        const float send = h4 ? v[0] : v[1];
        v[0] = keep + __shfl_xor_sync(0xffffffffu, send, 4);
    }
    v[0] += __shfl_xor_sync(0xffffffffu, v[0], 2);
    v[0] += __shfl_xor_sync(0xffffffffu, v[0], 1);
    return v[0];
}

// =============================================================================
// Fused kernel: modulator MLP + scan update u=0.  One CTA per neuron n,
// 512 threads.  Step-0 gathers read pm_in (fp32) directly — no cross-CTA
// dependency on the MLP — so the MLP's DRAM streaming overlaps step-0's
// latency-bound phase chip-wide.  Writes g_pmh[1].
// =============================================================================
__global__ void __launch_bounds__(512, 2) modstep0(
    const float* __restrict__ cc,   const float* __restrict__ h_in,
    const float* __restrict__ pm_in,
    const float* __restrict__ tp,   const float* __restrict__ tk,
    const float* __restrict__ prim, const float* __restrict__ keyp,
    const float* __restrict__ dlog, const float* __restrict__ fc1w,
    const float* __restrict__ fc1b, const float* __restrict__ fc2w,
    const float* __restrict__ fc2b, const float* __restrict__ mll,
    const float* __restrict__ bw,   const float* __restrict__ gw,
    const int* __restrict__ conn,   float* __restrict__ out)
{
    const int n   = blockIdx.x;
    const int tid = threadIdx.x;

    __shared__ __align__(16) float s_in[FIN * 12];      // [j][b] pad 12
    __shared__ float   s_part[8 * 8 * 64];              // [seg][b][h]
    __shared__ float   s_x[8 * 64];
    __shared__ float   s_o[24];
    __shared__ float   s_norm[16];
    __shared__ float   s_ep[8 * 64];                    // eff_prim  [b][d]
    __shared__ float   s_ek[8 * 64];                    // eff_key   [b][d]
    __shared__ float   s_ed[8];                         // eff_decay [b]
    __shared__ __half2 s_bwh[1024];                     // branch w  [k][d/2]
    __shared__ float   s_gw[256];                       // group w   [nb][d]
    __shared__ int     s_idx[32];

    // ---- early fills for the step phase (overlap with staging) ----
    #pragma unroll
    for (int i = 0; i < 2; i++) {
        const int idx = tid + 512 * i;
        const float2 v = *(const float2*)&bw[(size_t)n * 2048 + 2 * idx];
        s_bwh[idx] = __floats2half2_rn(v.x, v.y);
    }
    if (tid < 256) s_gw[tid] = gw[(size_t)n * 256 + tid];
    else if (tid < 288) s_idx[tid - 256] = conn[(size_t)n * KK + (tid - 256)];

    // ---- stage mod_input transposed: s_in[j*12 + b] ----
    for (int idx = tid; idx < BS * FIN; idx += 512) {
        const int b = idx / FIN, j = idx % FIN;
        float v;
        if      (j <  64) v = h_in[((size_t)b * NN + n) * DD + j];
        else if (j < 128) v = tp  [((size_t)b * NN + n) * DD + j - 64];
        else if (j < 192) v = tk  [((size_t)b * NN + n) * DD + j - 128];
        else if (j < 256) v = prim[(size_t)n * DD + j - 192];
        else              v = keyp[(size_t)n * DD + j - 256];
        s_in[j * 12 + b] = v;
    }
    __syncthreads();

    // ---- fc1: thread (seg,h), packed f32x2 over batch pairs ----
    {
        const int seg = tid >> 6, hh = tid & 63;
        u64 a[4] = {0ull, 0ull, 0ull, 0ull};
        const float* W = fc1w + (size_t)n * FIN * HH + hh;
        const int j0 = seg * 40;
        #pragma unroll 8
        for (int jj = 0; jj < 40; jj++) {
            const int j = j0 + jj;
            const float w = __ldcs(&W[(size_t)j * HH]);   // stream-once
            const u64 w2 = pk2(w, w);
            const u64* ip = (const u64*)&s_in[j * 12];
            a[0] = fma2(ip[0], w2, a[0]);
            a[1] = fma2(ip[1], w2, a[1]);
            a[2] = fma2(ip[2], w2, a[2]);
            a[3] = fma2(ip[3], w2, a[3]);
        }
        #pragma unroll
        for (int p = 0; p < 4; p++) {
            const float2 f = upk2(a[p]);
            s_part[((seg * 8) + 2 * p)     * 64 + hh] = f.x;
            s_part[((seg * 8) + 2 * p + 1) * 64 + hh] = f.y;
        }
    }
    __syncthreads();

    // ---- reduce segments, bias, tanh ----
    {
        const int b = tid >> 6, h = tid & 63;
        float s = 0.f;
        #pragma unroll
        for (int seg = 0; seg < 8; seg++) s += s_part[(seg * 8 + b) * 64 + h];
        s_x[b * 64 + h] = tanhfast(s + fc1b[(size_t)n * HH + h]);
    }
    __syncthreads();

    // ---- fc2 (24 threads) + trace norms (threads 32..47) ----
    if (tid < 24) {
        const int b = tid / 3, o = tid % 3;
        float acc = fc2b[(size_t)n * 3 + o];
        #pragma unroll 8
        for (int h = 0; h < 64; h++)
            acc += s_x[b * 64 + h] * fc2w[((size_t)n * 64 + h) * 3 + o];
        s_o[b * 3 + o] = acc;
    } else if (tid >= 32 && tid < 48) {
        const int q = tid - 32, b = q >> 1, which = q & 1;
        float s = 0.f;
        const int base = 64 + which * 64;
        #pragma unroll 8
        for (int d = 0; d < 64; d++) {
            const float v = s_in[(base + d) * 12 + b];
            s += v * v;
        }
        s_norm[b * 2 + which] = fmaxf(sqrtf(s), 1e-8f);
    }
    __syncthreads();

    // ---- finalize eff_* (smem + global for later steps) ----
    {
        const int b = tid >> 6, d = tid & 63;
        const float mod_lr = sigf(mll[0]);
        const float gp = tanhfast(s_o[b * 3 + 0]);
        const float gk = tanhfast(s_o[b * 3 + 1]);
        const float dm = s_o[b * 3 + 2];
        const float tpv = s_in[(64 + d) * 12 + b];
        const float tkv = s_in[(128 + d) * 12 + b];
        const size_t off = ((size_t)b * NN + n) * DD + d;
        const float ep = prim[(size_t)n * DD + d] + mod_lr * gp * (tpv / s_norm[b * 2 + 0]);
        const float ek = keyp[(size_t)n * DD + d] + mod_lr * gk * (tkv / s_norm[b * 2 + 1]);
        g_ep[off] = ep;  s_ep[b * 64 + d] = ep;
        g_ek[off] = ek;  s_ek[b * 64 + d] = ek;
        if (d == 0) {
            const float ed = sigf(dlog[n] + dm);
            g_ed[(size_t)b * NN + n] = ed;
            s_ed[b] = ed;
        }
    }
    __syncthreads();

    // =========================== step u=0 ===================================
    // warps 0..7 only (b = warp); gathers from pm_in (fp32).
    if (tid < 256) {
        const int b = tid >> 5, l = tid & 31;
        const float* pmb = pm_in + (size_t)b * NN * DD;
        const float2 key = *(const float2*)&s_ek[b * 64 + 2 * l];
        u64 accp[4];

        float2 m[8];
        #pragma unroll
        for (int kk = 0; kk < 8; kk++)
            m[kk] = __ldg((const float2*)&pmb[s_idx[kk] * DD + 2 * l]);

        #pragma unroll
        for (int c = 0; c < 4; c++) {
            float v[8];
            u64 t[8];
            #pragma unroll
            for (int kk = 0; kk < 8; kk++) {
                const float2 bwv = __half22float2(s_bwh[(c * 8 + kk) * 32 + l]);
                v[kk] = key.x * m[kk].x + key.y * m[kk].y;
                t[kk] = mul2(pk2(m[kk].x, m[kk].y), pk2(bwv.x, bwv.y));
            }
            if (c < 3) {
                #pragma unroll
                for (int kk = 0; kk < 8; kk++)
                    m[kk] = __ldg((const float2*)&pmb[s_idx[(c + 1) * 8 + kk] * DD + 2 * l]);
            }
            const float w = sigf(multireduce8(v, l));
            u64 a = 0ull;
            #pragma unroll
            for (int kk = 0; kk < 8; kk++) {
                const float wk = __shfl_sync(0xffffffffu, w, kk << 2);
                a = fma2(t[kk], pk2(wk, wk), a);
            }
            accp[c] = a;
        }

        float r0 = 0.f, r1 = 0.f;
        #pragma unroll
        for (int nb = 0; nb < 4; nb++) {
            const float2 av  = upk2(accp[nb]);
            const float2 gwv = *(const float2*)&s_gw[nb * 64 + 2 * l];
            r0 += tanhfast(av.x) * gwv.x;
            r1 += tanhfast(av.y) * gwv.y;
        }
        r0 = tanhfast(r0);
        r1 = tanhfast(r1);

        if (n < C_) {
            const float2 ccv = *(const float2*)&cc[(((size_t)b * T_) * C_ + n) * DD + 2 * l];
            r0 += ccv.x;
            r1 += ccv.y;
        }

        const size_t off = ((size_t)b * NN + n) * DD;
        const float ed = s_ed[b];
        const float h0 = s_in[(2 * l) * 12 + b];
        const float h1 = s_in[(2 * l + 1) * 12 + b];
        const float nh0 = ed * h0 + (1.f - ed) * r0;
        const float nh1 = ed * h1 + (1.f - ed) * r1;
        *(float2*)&g_h[off + 2 * l] = make_float2(nh0, nh1);
        const float p0 = tanhfast(nh0 * s_ep[b * 64 + 2 * l]);
        const float p1 = tanhfast(nh1 * s_ep[b * 64 + 2 * l + 1]);
        *((__half2*)(g_pmh[1] + off) + l) = __floats2half2_rn(p0, p1);

        if (n < C_) {
            #pragma unroll
            for (int tt = 0; tt < 4; tt++) {
                const size_t oo = (((size_t)b * T_ + tt) * C_ + n) * DD + 2 * l;
                *(float2*)&out[oo] = make_float2(p0, p1);
            }
        }
    }
}

// =============================================================================
// Kernel B: scan updates u>=1.  One CTA per neuron n, 8 warps = 8 batches.
// Messages + branch weights fp16 (math fp32); pipelined gathers; butterfly
// sims; packed f32x2 accumulate.  64-reg ceiling — 48-reg cap spilled (R4).
// =============================================================================
__global__ void __launch_bounds__(256, 4) stepk(
    int parity, int t0,
    const float* __restrict__ cc, const float* __restrict__ bw,
    const float* __restrict__ gw, const int* __restrict__ conn,
    float* __restrict__ out)
{
    __shared__ __half2 s_bwh[1024];
    __shared__ float   s_gw[256];
    __shared__ int     s_idx[32];

    const int n   = blockIdx.x;
    const int tid = threadIdx.x;
    const int b   = tid >> 5;
    const int l   = tid & 31;

    const __half* pm_in  = g_pmh[parity];
    __half*       pm_out = g_pmh[parity ^ 1];

    #pragma unroll
    for (int i = 0; i < 4; i++) {
        const int idx = tid + 256 * i;
        const float2 v = *(const float2*)&bw[(size_t)n * 2048 + 2 * idx];
        s_bwh[idx] = __floats2half2_rn(v.x, v.y);
    }
    s_gw[tid] = gw[(size_t)n * 256 + tid];
    if (tid < 32) s_idx[tid] = conn[(size_t)n * KK + tid];

    const size_t off = ((size_t)b * NN + n) * DD;
    const float2 key = *(const float2*)&g_ek[off + 2 * l];
    __syncthreads();

    const __half2* pmb = (const __half2*)(pm_in + (size_t)b * NN * DD);
    u64 accp[4];

    __half2 m[8];
    #pragma unroll
    for (int kk = 0; kk < 8; kk++)
        m[kk] = __ldg(&pmb[s_idx[kk] * 32 + l]);

    #pragma unroll
    for (int c = 0; c < 4; c++) {
        float v[8];
        u64 t[8];
        #pragma unroll
        for (int kk = 0; kk < 8; kk++) {
            const float2 mf  = __half22float2(m[kk]);
            const float2 bwv = __half22float2(s_bwh[(c * 8 + kk) * 32 + l]);
            v[kk] = key.x * mf.x + key.y * mf.y;
            t[kk] = mul2(pk2(mf.x, mf.y), pk2(bwv.x, bwv.y));
        }
        if (c < 3) {
            #pragma unroll
            for (int kk = 0; kk < 8; kk++)
                m[kk] = __ldg(&pmb[s_idx[(c + 1) * 8 + kk] * 32 + l]);
        }
        const float w = sigf(multireduce8(v, l));
        u64 a = 0ull;
        #pragma unroll
        for (int kk = 0; kk < 8; kk++) {
            const float wk = __shfl_sync(0xffffffffu, w, kk << 2);
            a = fma2(t[kk], pk2(wk, wk), a);
        }
        accp[c] = a;
    }

    float r0 = 0.f, r1 = 0.f;
    #pragma unroll
    for (int nb = 0; nb < 4; nb++) {
        const float2 av  = upk2(accp[nb]);
        const float2 gwv = *(const float2*)&s_gw[nb * 64 + 2 * l];
        r0 += tanhfast(av.x) * gwv.x;
        r1 += tanhfast(av.y) * gwv.y;
    }
    r0 = tanhfast(r0);
    r1 = tanhfast(r1);

    if (n < C_) {
        const float2 ccv = *(const float2*)&cc[(((size_t)b * T_ + t0) * C_ + n) * DD + 2 * l];
        r0 += ccv.x;
        r1 += ccv.y;
    }

    const float ed = g_ed[(size_t)b * NN + n];
    const float2 h = *(const float2*)&g_h[off + 2 * l];
    const float nh0 = ed * h.x + (1.f - ed) * r0;
    const float nh1 = ed * h.y + (1.f - ed) * r1;
    *(float2*)&g_h[off + 2 * l] = make_float2(nh0, nh1);
    const float2 ep = *(const float2*)&g_ep[off + 2 * l];
    const float p0 = tanhfast(nh0 * ep.x);
    const float p1 = tanhfast(nh1 * ep.y);
    *((__half2*)(pm_out + off) + l) = __floats2half2_rn(p0, p1);

    if (n < C_) {
        #pragma unroll
        for (int tt = 0; tt < 4; tt++) {
            const size_t oo = (((size_t)b * T_ + t0 + tt) * C_ + n) * DD + 2 * l;
            *(float2*)&out[oo] = make_float2(p0, p1);
        }
    }
}

// =============================================================================
extern "C" void kernel_launch(void* const* d_in, const int* in_sizes, int n_in,
                              void* d_out, int out_size)
{
    const float* cc    = (const float*)d_in[0];
    const float* h_in  = (const float*)d_in[1];
    const float* pm_in = (const float*)d_in[2];
    const float* tp    = (const float*)d_in[3];
    const float* tk    = (const float*)d_in[4];
    const float* prim  = (const float*)d_in[5];
    const float* keyp  = (const float*)d_in[6];
    const float* dlog  = (const float*)d_in[7];
    const float* bw    = (const float*)d_in[8];
    const float* gw    = (const float*)d_in[9];
    const float* fc1w  = (const float*)d_in[10];
    const float* fc1b  = (const float*)d_in[11];
    const float* fc2w  = (const float*)d_in[12];
    const float* fc2b  = (const float*)d_in[13];
    const float* mll   = (const float*)d_in[14];
    const int*   conn  = (const int*)d_in[15];
    float* out = (float*)d_out;

    // fused MLP + step0 (writes g_pmh[1])
    modstep0<<<NN, 512>>>(cc, h_in, pm_in, tp, tk, prim, keyp, dlog,
                          fc1w, fc1b, fc2w, fc2b, mll, bw, gw, conn, out);

    // steps u=1..7: parity = u&1 (u=1 reads g_pmh[1]) — unchanged scheme
    for (int u = 1; u < 8; u++) {
        stepk<<<NN, 256>>>(u & 1, 4 * u, cc, bw, gw, conn, out);
    }
}

// round 10
// speedup vs baseline: 1.0897x; 1.0897x over previous
#include <cuda_runtime.h>
#include <cuda_fp16.h>
#include <math.h>

#define BS   8
#define T_   32
#define C_   64
#define NN   4096
#define KK   32
#define DD   64
#define HH   64
#define FIN  320   // 5*D

// ---------------- persistent scratch (no allocation allowed) ----------------
__device__ __half g_pmh[2][BS * NN * DD];  // double-buffered messages (fp16)
__device__ float  g_h [BS * NN * DD];      // hidden state (fp32, in-place)
__device__ float  g_ep[BS * NN * DD];      // eff_prim
__device__ float  g_ek[BS * NN * DD];      // eff_key
__device__ float  g_ed[BS * NN];           // eff_decay (scalar per b,n)

// fast sigmoid
__device__ __forceinline__ float sigf(float x) {
    return __fdividef(1.f, 1.f + __expf(-x));
}
// fast tanh: 1 - 2/(e^{2x}+1).  Saturates correctly at +/-inf.
__device__ __forceinline__ float tanhfast(float x) {
    const float e = __expf(2.f * x);
    return 1.f - __fdividef(2.f, e + 1.f);
}

// ---- packed f32x2 helpers (Blackwell) ----
typedef unsigned long long u64;
__device__ __forceinline__ u64 pk2(float lo, float hi) {
    u64 r;
    asm("mov.b64 %0, {%1, %2};" : "=l"(r) : "f"(lo), "f"(hi));
    return r;
}
__device__ __forceinline__ float2 upk2(u64 v) {
    float2 r;
    asm("mov.b64 {%0, %1}, %2;" : "=f"(r.x), "=f"(r.y) : "l"(v));
    return r;
}
__device__ __forceinline__ u64 mul2(u64 a, u64 b) {
    u64 r;
    asm("mul.rn.f32x2 %0, %1, %2;" : "=l"(r) : "l"(a), "l"(b));
    return r;
}
__device__ __forceinline__ u64 fma2(u64 a, u64 b, u64 c) {
    u64 r;
    asm("fma.rn.f32x2 %0, %1, %2, %3;" : "=l"(r) : "l"(a), "l"(b), "l"(c));
    return r;
}

// =============================================================================
// Kernel A: modulator MLP + state init.  One CTA per neuron n, 512 threads.
// fc1 packed f32x2 over batch pairs; __ldcs on the stream-once fc1w; fc2 and
// trace-norm tails widened to 192/128 threads with a smem partial reduce.
// =============================================================================
__global__ void __launch_bounds__(512) modk(
    const float* __restrict__ h_in, const float* __restrict__ pm_in,
    const float* __restrict__ tp,   const float* __restrict__ tk,
    const float* __restrict__ prim, const float* __restrict__ keyp,
    const float* __restrict__ dlog, const float* __restrict__ fc1w,
    const float* __restrict__ fc1b, const float* __restrict__ fc2w,
    const float* __restrict__ fc2b, const float* __restrict__ mll)
{
    const int n   = blockIdx.x;
    const int tid = threadIdx.x;

    __shared__ __align__(16) float s_in[FIN * 12];      // [j][b] pad 12
    __shared__ float s_part[8 * 8 * 64];                // [seg][b][h]; tails reuse
    __shared__ float s_x[8 * 64];                       // tanh(fc1) activations
    __shared__ float s_o[24];                           // fc2 outputs [b][3]
    __shared__ float s_norm[16];                        // [b][{prim,key}]

    // ---- stage mod_input transposed: s_in[j*12 + b] ----
    for (int idx = tid; idx < BS * FIN; idx += 512) {
        const int b = idx / FIN, j = idx % FIN;
        float v;
        if      (j <  64) v = h_in[((size_t)b * NN + n) * DD + j];
        else if (j < 128) v = tp  [((size_t)b * NN + n) * DD + j - 64];
        else if (j < 192) v = tk  [((size_t)b * NN + n) * DD + j - 128];
        else if (j < 256) v = prim[(size_t)n * DD + j - 192];
        else              v = keyp[(size_t)n * DD + j - 256];
        s_in[j * 12 + b] = v;
    }
    __syncthreads();

    // ---- fc1: thread (seg,h), packed f32x2 over batch pairs ----
    {
        const int seg = tid >> 6, hh = tid & 63;
        u64 a[4] = {0ull, 0ull, 0ull, 0ull};
        const float* W = fc1w + (size_t)n * FIN * HH + hh;
        const int j0 = seg * 40;
        #pragma unroll 8
        for (int jj = 0; jj < 40; jj++) {
            const int j = j0 + jj;
            const float w = __ldcs(&W[(size_t)j * HH]);   // stream-once
            const u64 w2 = pk2(w, w);
            const u64* ip = (const u64*)&s_in[j * 12];
            a[0] = fma2(ip[0], w2, a[0]);
            a[1] = fma2(ip[1], w2, a[1]);
            a[2] = fma2(ip[2], w2, a[2]);
            a[3] = fma2(ip[3], w2, a[3]);
        }
        #pragma unroll
        for (int p = 0; p < 4; p++) {
            const float2 f = upk2(a[p]);
            s_part[((seg * 8) + 2 * p)     * 64 + hh] = f.x;
            s_part[((seg * 8) + 2 * p + 1) * 64 + hh] = f.y;
        }
    }
    __syncthreads();

    // ---- reduce segments, bias, tanh ----
    {
        const int b = tid >> 6, h = tid & 63;
        float s = 0.f;
        #pragma unroll
        for (int seg = 0; seg < 8; seg++) s += s_part[(seg * 8 + b) * 64 + h];
        s_x[b * 64 + h] = tanhfast(s + fc1b[(size_t)n * HH + h]);
    }
    __syncthreads();

    // ---- fc2 partials (192 threads) + norm partials (128 threads) ----
    if (tid < 192) {
        const int o = tid % 3, b = (tid / 3) & 7, hc = tid / 24;  // hc 0..7
        float acc = 0.f;
        #pragma unroll
        for (int i = 0; i < 8; i++) {
            const int h = hc * 8 + i;
            acc += s_x[b * 64 + h] * fc2w[((size_t)n * 64 + h) * 3 + o];
        }
        s_part[hc * 24 + b * 3 + o] = acc;
    } else if (tid < 320) {
        const int q = tid - 192;
        const int b = q >> 4, which = (q >> 3) & 1, dc = q & 7;
        float s = 0.f;
        const int base = 64 + which * 64 + dc * 8;
        #pragma unroll
        for (int i = 0; i < 8; i++) {
            const float v = s_in[(base + i) * 12 + b];
            s += v * v;
        }
        s_part[256 + (b * 2 + which) * 8 + dc] = s;
    }
    __syncthreads();

    // ---- final fc2 reduce (24 threads) + norm reduce (16 threads) ----
    if (tid < 24) {
        float acc = fc2b[(size_t)n * 3 + tid];
        #pragma unroll
        for (int hc = 0; hc < 8; hc++) acc += s_part[hc * 24 + tid];
        s_o[tid] = acc;
    } else if (tid >= 32 && tid < 48) {
        const int q = tid - 32;
        float s = 0.f;
        #pragma unroll
        for (int i = 0; i < 8; i++) s += s_part[256 + q * 8 + i];
        s_norm[q] = fmaxf(sqrtf(s), 1e-8f);
    }
    __syncthreads();

    // ---- finalize eff_* and init state ----
    {
        const int b = tid >> 6, d = tid & 63;
        const float mod_lr = sigf(mll[0]);
        const float gp = tanhfast(s_o[b * 3 + 0]);
        const float gk = tanhfast(s_o[b * 3 + 1]);
        const float dm = s_o[b * 3 + 2];
        const float tpv = s_in[(64 + d) * 12 + b];
        const float tkv = s_in[(128 + d) * 12 + b];
        const size_t off = ((size_t)b * NN + n) * DD + d;
        g_ep[off] = prim[(size_t)n * DD + d] + mod_lr * gp * (tpv / s_norm[b * 2 + 0]);
        g_ek[off] = keyp[(size_t)n * DD + d] + mod_lr * gk * (tkv / s_norm[b * 2 + 1]);
        g_h [off] = s_in[d * 12 + b];
        g_pmh[0][off] = __float2half_rn(pm_in[off]);
        if (d == 0) g_ed[(size_t)b * NN + n] = sigf(dlog[n] + dm);
    }
}

// =============================================================================
// Kernel B: one scan update.  One CTA per neuron n, 8 warps = 8 batches.
// Pipeline-4 redesign: chunks of 4 k with a 4-deep half2 prefetch buffer.
// No premul t[] (m*bw recomputed after w is known) and no accp[] (branch tanh
// folded into odd chunks) -> ~44-reg working set so (256,5) gives 5 CTAs/SM
// without the forced-spill failure of R4.
// =============================================================================
__global__ void __launch_bounds__(256, 5) stepk(
    int parity, int t0,
    const float* __restrict__ cc, const float* __restrict__ bw,
    const float* __restrict__ gw, const int* __restrict__ conn,
    float* __restrict__ out)
{
    __shared__ __half2 s_bwh[1024];   // [k][d/2]  fp16 branch weights
    __shared__ float   s_gw[256];     // [nb][d]   fp32 group weights
    __shared__ int     s_idx[32];

    const int n   = blockIdx.x;
    const int tid = threadIdx.x;
    const int b   = tid >> 5;
    const int l   = tid & 31;

    const __half* pm_in  = g_pmh[parity];
    __half*       pm_out = g_pmh[parity ^ 1];

    #pragma unroll
    for (int i = 0; i < 4; i++) {
        const int idx = tid + 256 * i;
        const float2 v = *(const float2*)&bw[(size_t)n * 2048 + 2 * idx];
        s_bwh[idx] = __floats2half2_rn(v.x, v.y);
    }
    s_gw[tid] = gw[(size_t)n * 256 + tid];
    if (tid < 32) s_idx[tid] = conn[(size_t)n * KK + tid];

    const size_t off = ((size_t)b * NN + n) * DD;
    const float2 key = *(const float2*)&g_ek[off + 2 * l];
    __syncthreads();

    const __half2* pmb = (const __half2*)(pm_in + (size_t)b * NN * DD);

    __half2 mc[4], mn[4];
    #pragma unroll
    for (int kk = 0; kk < 4; kk++)
        mc[kk] = __ldg(&pmb[s_idx[kk] * 32 + l]);

    float r0 = 0.f, r1 = 0.f;
    u64 acc = 0ull;

    #pragma unroll
    for (int c = 0; c < 8; c++) {
        // ---- sim partials from current 4 messages ----
        float v[4];
        #pragma unroll
        for (int kk = 0; kk < 4; kk++) {
            const float2 mf = __half22float2(mc[kk]);
            v[kk] = key.x * mf.x + key.y * mf.y;
        }

        // ---- prefetch next chunk (overlaps reduce + accumulate) ----
        if (c < 7) {
            #pragma unroll
            for (int kk = 0; kk < 4; kk++)
                mn[kk] = __ldg(&pmb[s_idx[(c + 1) * 4 + kk] * 32 + l]);
        }

        // ---- multireduce4: 4 sums over 32 lanes; lane l ends with kk=(l>>3)&3
        {
            const bool h16 = (l & 16);
            float a0 = (h16 ? v[2] : v[0]) + __shfl_xor_sync(0xffffffffu, h16 ? v[0] : v[2], 16);
            float a1 = (h16 ? v[3] : v[1]) + __shfl_xor_sync(0xffffffffu, h16 ? v[1] : v[3], 16);
            const bool h8 = (l & 8);
            float b0 = (h8 ? a1 : a0) + __shfl_xor_sync(0xffffffffu, h8 ? a0 : a1, 8);
            b0 += __shfl_xor_sync(0xffffffffu, b0, 4);
            b0 += __shfl_xor_sync(0xffffffffu, b0, 2);
            b0 += __shfl_xor_sync(0xffffffffu, b0, 1);
            v[0] = b0;
        }
        const float w = sigf(v[0]);

        // ---- accumulate: acc += (m*bw) * w_k  (m reconverted, no t[] regs) ----
        #pragma unroll
        for (int kk = 0; kk < 4; kk++) {
            const float wk = __shfl_sync(0xffffffffu, w, kk << 3);
            const float2 mf  = __half22float2(mc[kk]);
            const float2 bwv = __half22float2(s_bwh[(c * 4 + kk) * 32 + l]);
            acc = fma2(mul2(pk2(mf.x, mf.y), pk2(bwv.x, bwv.y)), pk2(wk, wk), acc);
        }

        // ---- branch boundary every 2 chunks: fold tanh into r0/r1 ----
        if (c & 1) {
            const int nb = c >> 1;
            const float2 av  = upk2(acc);
            const float2 gwv = *(const float2*)&s_gw[nb * 64 + 2 * l];
            r0 += tanhfast(av.x) * gwv.x;
            r1 += tanhfast(av.y) * gwv.y;
            acc = 0ull;
        }

        #pragma unroll
        for (int kk = 0; kk < 4; kk++) mc[kk] = mn[kk];
    }

    r0 = tanhfast(r0);
    r1 = tanhfast(r1);

    if (n < C_) {   // cc injection on first C neurons
        const float2 ccv = *(const float2*)&cc[(((size_t)b * T_ + t0) * C_ + n) * DD + 2 * l];
        r0 += ccv.x;
        r1 += ccv.y;
    }

    // ---- h / message update ----
    const float ed = g_ed[(size_t)b * NN + n];
    const float2 h = *(const float2*)&g_h[off + 2 * l];
    const float nh0 = ed * h.x + (1.f - ed) * r0;
    const float nh1 = ed * h.y + (1.f - ed) * r1;
    *(float2*)&g_h[off + 2 * l] = make_float2(nh0, nh1);
    const float2 ep = *(const float2*)&g_ep[off + 2 * l];
    const float p0 = tanhfast(nh0 * ep.x);
    const float p1 = tanhfast(nh1 * ep.y);
    *((__half2*)(pm_out + off) + l) = __floats2half2_rn(p0, p1);

    if (n < C_) {   // emit the 4 timesteps this update covers (fp32 output)
        #pragma unroll
        for (int tt = 0; tt < 4; tt++) {
            const size_t oo = (((size_t)b * T_ + t0 + tt) * C_ + n) * DD + 2 * l;
            *(float2*)&out[oo] = make_float2(p0, p1);
        }
    }
}

// =============================================================================
extern "C" void kernel_launch(void* const* d_in, const int* in_sizes, int n_in,
                              void* d_out, int out_size)
{
    const float* cc    = (const float*)d_in[0];
    const float* h_in  = (const float*)d_in[1];
    const float* pm_in = (const float*)d_in[2];
    const float* tp    = (const float*)d_in[3];
    const float* tk    = (const float*)d_in[4];
    const float* prim  = (const float*)d_in[5];
    const float* keyp  = (const float*)d_in[6];
    const float* dlog  = (const float*)d_in[7];
    const float* bw    = (const float*)d_in[8];
    const float* gw    = (const float*)d_in[9];
    const float* fc1w  = (const float*)d_in[10];
    const float* fc1b  = (const float*)d_in[11];
    const float* fc2w  = (const float*)d_in[12];
    const float* fc2b  = (const float*)d_in[13];
    const float* mll   = (const float*)d_in[14];
    const int*   conn  = (const int*)d_in[15];
    float* out = (float*)d_out;

    modk<<<NN, 512>>>(h_in, pm_in, tp, tk, prim, keyp, dlog,
                      fc1w, fc1b, fc2w, fc2b, mll);

    // stride = 4 (fixed by setup): updates at t = 0,4,...,28; output replicated x4
    for (int u = 0; u < 8; u++) {
        stepk<<<NN, 256>>>(u & 1, 4 * u, cc, bw, gw, conn, out);
    }
}

// round 11
// speedup vs baseline: 1.1546x; 1.0596x over previous
#include <cuda_runtime.h>
#include <cuda_fp16.h>
#include <math.h>

#define BS   8
#define T_   32
#define C_   64
#define NN   4096
#define KK   32
#define DD   64
#define HH   64
#define FIN  320   // 5*D

// ---------------- persistent scratch (no allocation allowed) ----------------
__device__ __half g_pmh[2][BS * NN * DD];  // double-buffered messages (fp16)
__device__ float  g_h [BS * NN * DD];      // hidden state (fp32, in-place)
__device__ float  g_ep[BS * NN * DD];      // eff_prim
__device__ float  g_ek[BS * NN * DD];      // eff_key
__device__ float  g_ed[BS * NN];           // eff_decay (scalar per b,n)

// fast sigmoid
__device__ __forceinline__ float sigf(float x) {
    return __fdividef(1.f, 1.f + __expf(-x));
}
// fast tanh: 1 - 2/(e^{2x}+1).  Saturates correctly at +/-inf.  ~1e-6 rel.
__device__ __forceinline__ float tanhfast(float x) {
    const float e = __expf(2.f * x);
    return 1.f - __fdividef(2.f, e + 1.f);
}
// HW tanh (1 MUFU op, ~2^-10 rel err).  ONLY for inner branch tanhs whose
// error is damped ~10x before the output; final tanhs stay on tanhfast.
__device__ __forceinline__ float tanha(float x) {
    float y;
    asm("tanh.approx.f32 %0, %1;" : "=f"(y) : "f"(x));
    return y;
}

// ---- packed f32x2 helpers (Blackwell) ----
typedef unsigned long long u64;
__device__ __forceinline__ u64 pk2(float lo, float hi) {
    u64 r;
    asm("mov.b64 %0, {%1, %2};" : "=l"(r) : "f"(lo), "f"(hi));
    return r;
}
__device__ __forceinline__ float2 upk2(u64 v) {
    float2 r;
    asm("mov.b64 {%0, %1}, %2;" : "=f"(r.x), "=f"(r.y) : "l"(v));
    return r;
}
__device__ __forceinline__ u64 mul2(u64 a, u64 b) {
    u64 r;
    asm("mul.rn.f32x2 %0, %1, %2;" : "=l"(r) : "l"(a), "l"(b));
    return r;
}
__device__ __forceinline__ u64 fma2(u64 a, u64 b, u64 c) {
    u64 r;
    asm("fma.rn.f32x2 %0, %1, %2, %3;" : "=l"(r) : "l"(a), "l"(b), "l"(c));
    return r;
}

// butterfly multi-reduce: 8 sums over 32 lanes; lane l ends with sum for
// kk = (l>>2)&7
__device__ __forceinline__ float multireduce8(float v[8], int l) {
    const bool h16 = (l & 16);
    #pragma unroll
    for (int i = 0; i < 4; i++) {
        const float keep = h16 ? v[4 + i] : v[i];
        const float send = h16 ? v[i]     : v[4 + i];
        v[i] = keep + __shfl_xor_sync(0xffffffffu, send, 16);
    }
    const bool h8 = (l & 8);
    #pragma unroll
    for (int i = 0; i < 2; i++) {
        const float keep = h8 ? v[2 + i] : v[i];
        const float send = h8 ? v[i]     : v[2 + i];
        v[i] = keep + __shfl_xor_sync(0xffffffffu, send, 8);
    }
    const bool h4 = (l & 4);
    {
        const float keep = h4 ? v[1] : v[0];
        const float send = h4 ? v[0] : v[1];
        v[0] = keep + __shfl_xor_sync(0xffffffffu, send, 4);
    }
    v[0] += __shfl_xor_sync(0xffffffffu, v[0], 2);
    v[0] += __shfl_xor_sync(0xffffffffu, v[0], 1);
    return v[0];
}

// =============================================================================
// Kernel A: modulator MLP + state init.  One CTA per neuron n, 512 threads.
// DRAM-stream-bound (~5.1 TB/s incl. 335 MB fc1w) — near its roof.
// =============================================================================
__global__ void __launch_bounds__(512) modk(
    const float* __restrict__ h_in, const float* __restrict__ pm_in,
    const float* __restrict__ tp,   const float* __restrict__ tk,
    const float* __restrict__ prim, const float* __restrict__ keyp,
    const float* __restrict__ dlog, const float* __restrict__ fc1w,
    const float* __restrict__ fc1b, const float* __restrict__ fc2w,
    const float* __restrict__ fc2b, const float* __restrict__ mll)
{
    const int n   = blockIdx.x;
    const int tid = threadIdx.x;

    __shared__ __align__(16) float s_in[FIN * 12];      // [j][b] pad 12
    __shared__ float s_part[8 * 8 * 64];                // [seg][b][h]; tails reuse
    __shared__ float s_x[8 * 64];                       // tanh(fc1) activations
    __shared__ float s_o[24];                           // fc2 outputs [b][3]
    __shared__ float s_norm[16];                        // [b][{prim,key}]

    // ---- stage mod_input transposed: s_in[j*12 + b] ----
    for (int idx = tid; idx < BS * FIN; idx += 512) {
        const int b = idx / FIN, j = idx % FIN;
        float v;
        if      (j <  64) v = h_in[((size_t)b * NN + n) * DD + j];
        else if (j < 128) v = tp  [((size_t)b * NN + n) * DD + j - 64];
        else if (j < 192) v = tk  [((size_t)b * NN + n) * DD + j - 128];
        else if (j < 256) v = prim[(size_t)n * DD + j - 192];
        else              v = keyp[(size_t)n * DD + j - 256];
        s_in[j * 12 + b] = v;
    }
    __syncthreads();

    // ---- fc1: thread (seg,h), packed f32x2 over batch pairs ----
    {
        const int seg = tid >> 6, hh = tid & 63;
        u64 a[4] = {0ull, 0ull, 0ull, 0ull};
        const float* W = fc1w + (size_t)n * FIN * HH + hh;
        const int j0 = seg * 40;
        #pragma unroll 8
        for (int jj = 0; jj < 40; jj++) {
            const int j = j0 + jj;
            const float w = __ldcs(&W[(size_t)j * HH]);   // stream-once
            const u64 w2 = pk2(w, w);
            const u64* ip = (const u64*)&s_in[j * 12];
            a[0] = fma2(ip[0], w2, a[0]);
            a[1] = fma2(ip[1], w2, a[1]);
            a[2] = fma2(ip[2], w2, a[2]);
            a[3] = fma2(ip[3], w2, a[3]);
        }
        #pragma unroll
        for (int p = 0; p < 4; p++) {
            const float2 f = upk2(a[p]);
            s_part[((seg * 8) + 2 * p)     * 64 + hh] = f.x;
            s_part[((seg * 8) + 2 * p + 1) * 64 + hh] = f.y;
        }
    }
    __syncthreads();

    // ---- reduce segments, bias, tanh ----
    {
        const int b = tid >> 6, h = tid & 63;
        float s = 0.f;
        #pragma unroll
        for (int seg = 0; seg < 8; seg++) s += s_part[(seg * 8 + b) * 64 + h];
        s_x[b * 64 + h] = tanhfast(s + fc1b[(size_t)n * HH + h]);
    }
    __syncthreads();

    // ---- fc2 partials (192 threads) + norm partials (128 threads) ----
    if (tid < 192) {
        const int o = tid % 3, b = (tid / 3) & 7, hc = tid / 24;  // hc 0..7
        float acc = 0.f;
        #pragma unroll
        for (int i = 0; i < 8; i++) {
            const int h = hc * 8 + i;
            acc += s_x[b * 64 + h] * fc2w[((size_t)n * 64 + h) * 3 + o];
        }
        s_part[hc * 24 + b * 3 + o] = acc;
    } else if (tid < 320) {
        const int q = tid - 192;
        const int b = q >> 4, which = (q >> 3) & 1, dc = q & 7;
        float s = 0.f;
        const int base = 64 + which * 64 + dc * 8;
        #pragma unroll
        for (int i = 0; i < 8; i++) {
            const float v = s_in[(base + i) * 12 + b];
            s += v * v;
        }
        s_part[256 + (b * 2 + which) * 8 + dc] = s;
    }
    __syncthreads();

    // ---- final fc2 reduce (24 threads) + norm reduce (16 threads) ----
    if (tid < 24) {
        float acc = fc2b[(size_t)n * 3 + tid];
        #pragma unroll
        for (int hc = 0; hc < 8; hc++) acc += s_part[hc * 24 + tid];
        s_o[tid] = acc;
    } else if (tid >= 32 && tid < 48) {
        const int q = tid - 32;
        float s = 0.f;
        #pragma unroll
        for (int i = 0; i < 8; i++) s += s_part[256 + q * 8 + i];
        s_norm[q] = fmaxf(sqrtf(s), 1e-8f);
    }
    __syncthreads();

    // ---- finalize eff_* and init state ----
    {
        const int b = tid >> 6, d = tid & 63;
        const float mod_lr = sigf(mll[0]);
        const float gp = tanhfast(s_o[b * 3 + 0]);
        const float gk = tanhfast(s_o[b * 3 + 1]);
        const float dm = s_o[b * 3 + 2];
        const float tpv = s_in[(64 + d) * 12 + b];
        const float tkv = s_in[(128 + d) * 12 + b];
        const size_t off = ((size_t)b * NN + n) * DD + d;
        g_ep[off] = prim[(size_t)n * DD + d] + mod_lr * gp * (tpv / s_norm[b * 2 + 0]);
        g_ek[off] = keyp[(size_t)n * DD + d] + mod_lr * gk * (tkv / s_norm[b * 2 + 1]);
        g_h [off] = s_in[d * 12 + b];
        g_pmh[0][off] = __float2half_rn(pm_in[off]);
        if (d == 0) g_ed[(size_t)b * NN + n] = sigf(dlog[n] + dm);
    }
}

// =============================================================================
// Kernel B: one scan update.  R8 shape (validated 34.75us): pipeline-8,
// premul t[], packed f32x2 accumulate, 64-reg ceiling at 4 CTAs/SM.
// R10 lesson: stepk is ISSUE-bound — more occupancy (pipeline-4, 5 CTAs/SM)
// was slower.  R4 lesson: 48-reg cap spills the gather batch.
// Change vs R8: branch tanhs use HW tanh.approx (1 MUFU vs ~6 ops) — inner
// position damps its 2^-10 error ~10x before the output.
// =============================================================================
__global__ void __launch_bounds__(256, 4) stepk(
    int parity, int t0,
    const float* __restrict__ cc, const float* __restrict__ bw,
    const float* __restrict__ gw, const int* __restrict__ conn,
    float* __restrict__ out)
{
    __shared__ __half2 s_bwh[1024];   // [k][d/2]  fp16 branch weights
    __shared__ float   s_gw[256];     // [nb][d]   fp32 group weights
    __shared__ int     s_idx[32];

    const int n   = blockIdx.x;
    const int tid = threadIdx.x;
    const int b   = tid >> 5;
    const int l   = tid & 31;

    const __half* pm_in  = g_pmh[parity];
    __half*       pm_out = g_pmh[parity ^ 1];

    #pragma unroll
    for (int i = 0; i < 4; i++) {
        const int idx = tid + 256 * i;
        const float2 v = *(const float2*)&bw[(size_t)n * 2048 + 2 * idx];
        s_bwh[idx] = __floats2half2_rn(v.x, v.y);
    }
    s_gw[tid] = gw[(size_t)n * 256 + tid];
    if (tid < 32) s_idx[tid] = conn[(size_t)n * KK + tid];

    const size_t off = ((size_t)b * NN + n) * DD;
    const float2 key = *(const float2*)&g_ek[off + 2 * l];
    __syncthreads();

    const __half2* pmb = (const __half2*)(pm_in + (size_t)b * NN * DD);
    u64 accp[4];

    __half2 m[8];
    #pragma unroll
    for (int kk = 0; kk < 8; kk++)
        m[kk] = __ldg(&pmb[s_idx[kk] * 32 + l]);

    #pragma unroll
    for (int c = 0; c < 4; c++) {
        float v[8];
        u64 t[8];
        #pragma unroll
        for (int kk = 0; kk < 8; kk++) {
            const float2 mf  = __half22float2(m[kk]);
            const float2 bwv = __half22float2(s_bwh[(c * 8 + kk) * 32 + l]);
            v[kk] = key.x * mf.x + key.y * mf.y;
            t[kk] = mul2(pk2(mf.x, mf.y), pk2(bwv.x, bwv.y));
        }
        if (c < 3) {
            #pragma unroll
            for (int kk = 0; kk < 8; kk++)
                m[kk] = __ldg(&pmb[s_idx[(c + 1) * 8 + kk] * 32 + l]);
        }
        const float w = sigf(multireduce8(v, l));
        u64 a = 0ull;
        #pragma unroll
        for (int kk = 0; kk < 8; kk++) {
            const float wk = __shfl_sync(0xffffffffu, w, kk << 2);
            a = fma2(t[kk], pk2(wk, wk), a);
        }
        accp[c] = a;
    }

    // ---- branch tanh (HW approx) -> group sum -> group tanh (precise) ----
    float r0 = 0.f, r1 = 0.f;
    #pragma unroll
    for (int nb = 0; nb < 4; nb++) {
        const float2 av  = upk2(accp[nb]);
        const float2 gwv = *(const float2*)&s_gw[nb * 64 + 2 * l];
        r0 += tanha(av.x) * gwv.x;
        r1 += tanha(av.y) * gwv.y;
    }
    r0 = tanhfast(r0);
    r1 = tanhfast(r1);

    if (n < C_) {   // cc injection on first C neurons
        const float2 ccv = *(const float2*)&cc[(((size_t)b * T_ + t0) * C_ + n) * DD + 2 * l];
        r0 += ccv.x;
        r1 += ccv.y;
    }

    // ---- h / message update ----
    const float ed = g_ed[(size_t)b * NN + n];
    const float2 h = *(const float2*)&g_h[off + 2 * l];
    const float nh0 = ed * h.x + (1.f - ed) * r0;
    const float nh1 = ed * h.y + (1.f - ed) * r1;
    *(float2*)&g_h[off + 2 * l] = make_float2(nh0, nh1);
    const float2 ep = *(const float2*)&g_ep[off + 2 * l];
    const float p0 = tanhfast(nh0 * ep.x);
    const float p1 = tanhfast(nh1 * ep.y);
    *((__half2*)(pm_out + off) + l) = __floats2half2_rn(p0, p1);

    if (n < C_) {   // emit the 4 timesteps this update covers (fp32 output)
        #pragma unroll
        for (int tt = 0; tt < 4; tt++) {
            const size_t oo = (((size_t)b * T_ + t0 + tt) * C_ + n) * DD + 2 * l;
            *(float2*)&out[oo] = make_float2(p0, p1);
        }
    }
}

// =============================================================================
extern "C" void kernel_launch(void* const* d_in, const int* in_sizes, int n_in,
                              void* d_out, int out_size)
{
    const float* cc    = (const float*)d_in[0];
    const float* h_in  = (const float*)d_in[1];
    const float* pm_in = (const float*)d_in[2];
    const float* tp    = (const float*)d_in[3];
    const float* tk    = (const float*)d_in[4];
    const float* prim  = (const float*)d_in[5];
    const float* keyp  = (const float*)d_in[6];
    const float* dlog  = (const float*)d_in[7];
    const float* bw    = (const float*)d_in[8];
    const float* gw    = (const float*)d_in[9];
    const float* fc1w  = (const float*)d_in[10];
    const float* fc1b  = (const float*)d_in[11];
    const float* fc2w  = (const float*)d_in[12];
    const float* fc2b  = (const float*)d_in[13];
    const float* mll   = (const float*)d_in[14];
    const int*   conn  = (const int*)d_in[15];
    float* out = (float*)d_out;

    modk<<<NN, 512>>>(h_in, pm_in, tp, tk, prim, keyp, dlog,
                      fc1w, fc1b, fc2w, fc2b, mll);

    // stride = 4 (fixed by setup): updates at t = 0,4,...,28; output replicated x4
    for (int u = 0; u < 8; u++) {
        stepk<<<NN, 256>>>(u & 1, 4 * u, cc, bw, gw, conn, out);
    }
}

// round 12
// speedup vs baseline: 1.2187x; 1.0555x over previous
#include <cuda_runtime.h>
#include <cuda_fp16.h>
#include <math.h>

#define BS   8
#define T_   32
#define C_   64
#define NN   4096
#define KK   32
#define DD   64
#define HH   64
#define FIN  320   // 5*D

// ---------------- persistent scratch (no allocation allowed) ----------------
__device__ __half g_pmh[2][BS * NN * DD];  // double-buffered messages (fp16)
__device__ float  g_h [BS * NN * DD];      // hidden state (fp32, in-place)
__device__ float  g_ep[BS * NN * DD];      // eff_prim
__device__ float  g_ek[BS * NN * DD];      // eff_key
__device__ float  g_ed[BS * NN];           // eff_decay (scalar per b,n)

// fast sigmoid (precise-ish, for modk)
__device__ __forceinline__ float sigf(float x) {
    return __fdividef(1.f, 1.f + __expf(-x));
}
// fast tanh: 1 - 2/(e^{2x}+1).  Saturates correctly at +/-inf.  ~1e-6 rel.
__device__ __forceinline__ float tanhfast(float x) {
    const float e = __expf(2.f * x);
    return 1.f - __fdividef(2.f, e + 1.f);
}
// HW tanh (1 MUFU op, ~5e-4 max abs err).  Inner uses only; error damped
// before the output.  Final pm/out tanh stays tanhfast.
__device__ __forceinline__ float tanha(float x) {
    float y;
    asm("tanh.approx.f32 %0, %1;" : "=f"(y) : "f"(x));
    return y;
}
// sigmoid via HW tanh: 0.5 + 0.5*tanh(x/2)  (3 ops vs 5)
__device__ __forceinline__ float sigt(float x) {
    return fmaf(tanha(0.5f * x), 0.5f, 0.5f);
}

// ---- packed f32x2 helpers (Blackwell) ----
typedef unsigned long long u64;
__device__ __forceinline__ u64 pk2(float lo, float hi) {
    u64 r;
    asm("mov.b64 %0, {%1, %2};" : "=l"(r) : "f"(lo), "f"(hi));
    return r;
}
__device__ __forceinline__ float2 upk2(u64 v) {
    float2 r;
    asm("mov.b64 {%0, %1}, %2;" : "=f"(r.x), "=f"(r.y) : "l"(v));
    return r;
}
__device__ __forceinline__ u64 fma2(u64 a, u64 b, u64 c) {
    u64 r;
    asm("fma.rn.f32x2 %0, %1, %2, %3;" : "=l"(r) : "l"(a), "l"(b), "l"(c));
    return r;
}

// butterfly multi-reduce: 8 sums over 32 lanes; lane l ends with sum for
// kk = (l>>2)&7
__device__ __forceinline__ float multireduce8(float v[8], int l) {
    const bool h16 = (l & 16);
    #pragma unroll
    for (int i = 0; i < 4; i++) {
        const float keep = h16 ? v[4 + i] : v[i];
        const float send = h16 ? v[i]     : v[4 + i];
        v[i] = keep + __shfl_xor_sync(0xffffffffu, send, 16);
    }
    const bool h8 = (l & 8);
    #pragma unroll
    for (int i = 0; i < 2; i++) {
        const float keep = h8 ? v[2 + i] : v[i];
        const float send = h8 ? v[i]     : v[2 + i];
        v[i] = keep + __shfl_xor_sync(0xffffffffu, send, 8);
    }
    const bool h4 = (l & 4);
    {
        const float keep = h4 ? v[1] : v[0];
        const float send = h4 ? v[0] : v[1];
        v[0] = keep + __shfl_xor_sync(0xffffffffu, send, 4);
    }
    v[0] += __shfl_xor_sync(0xffffffffu, v[0], 2);
    v[0] += __shfl_xor_sync(0xffffffffu, v[0], 1);
    return v[0];
}

// =============================================================================
// Kernel A: modulator MLP + state init.  One CTA per neuron n, 512 threads.
// DRAM-stream-bound — near its roof; unchanged from R11.
// =============================================================================
__global__ void __launch_bounds__(512) modk(
    const float* __restrict__ h_in, const float* __restrict__ pm_in,
    const float* __restrict__ tp,   const float* __restrict__ tk,
    const float* __restrict__ prim, const float* __restrict__ keyp,
    const float* __restrict__ dlog, const float* __restrict__ fc1w,
    const float* __restrict__ fc1b, const float* __restrict__ fc2w,
    const float* __restrict__ fc2b, const float* __restrict__ mll)
{
    const int n   = blockIdx.x;
    const int tid = threadIdx.x;

    __shared__ __align__(16) float s_in[FIN * 12];      // [j][b] pad 12
    __shared__ float s_part[8 * 8 * 64];                // [seg][b][h]; tails reuse
    __shared__ float s_x[8 * 64];                       // tanh(fc1) activations
    __shared__ float s_o[24];                           // fc2 outputs [b][3]
    __shared__ float s_norm[16];                        // [b][{prim,key}]

    // ---- stage mod_input transposed: s_in[j*12 + b] ----
    for (int idx = tid; idx < BS * FIN; idx += 512) {
        const int b = idx / FIN, j = idx % FIN;
        float v;
        if      (j <  64) v = h_in[((size_t)b * NN + n) * DD + j];
        else if (j < 128) v = tp  [((size_t)b * NN + n) * DD + j - 64];
        else if (j < 192) v = tk  [((size_t)b * NN + n) * DD + j - 128];
        else if (j < 256) v = prim[(size_t)n * DD + j - 192];
        else              v = keyp[(size_t)n * DD + j - 256];
        s_in[j * 12 + b] = v;
    }
    __syncthreads();

    // ---- fc1: thread (seg,h), packed f32x2 over batch pairs ----
    {
        const int seg = tid >> 6, hh = tid & 63;
        u64 a[4] = {0ull, 0ull, 0ull, 0ull};
        const float* W = fc1w + (size_t)n * FIN * HH + hh;
        const int j0 = seg * 40;
        #pragma unroll 8
        for (int jj = 0; jj < 40; jj++) {
            const int j = j0 + jj;
            const float w = __ldcs(&W[(size_t)j * HH]);   // stream-once
            const u64 w2 = pk2(w, w);
            const u64* ip = (const u64*)&s_in[j * 12];
            a[0] = fma2(ip[0], w2, a[0]);
            a[1] = fma2(ip[1], w2, a[1]);
            a[2] = fma2(ip[2], w2, a[2]);
            a[3] = fma2(ip[3], w2, a[3]);
        }
        #pragma unroll
        for (int p = 0; p < 4; p++) {
            const float2 f = upk2(a[p]);
            s_part[((seg * 8) + 2 * p)     * 64 + hh] = f.x;
            s_part[((seg * 8) + 2 * p + 1) * 64 + hh] = f.y;
        }
    }
    __syncthreads();

    // ---- reduce segments, bias, tanh ----
    {
        const int b = tid >> 6, h = tid & 63;
        float s = 0.f;
        #pragma unroll
        for (int seg = 0; seg < 8; seg++) s += s_part[(seg * 8 + b) * 64 + h];
        s_x[b * 64 + h] = tanhfast(s + fc1b[(size_t)n * HH + h]);
    }
    __syncthreads();

    // ---- fc2 partials (192 threads) + norm partials (128 threads) ----
    if (tid < 192) {
        const int o = tid % 3, b = (tid / 3) & 7, hc = tid / 24;  // hc 0..7
        float acc = 0.f;
        #pragma unroll
        for (int i = 0; i < 8; i++) {
            const int h = hc * 8 + i;
            acc += s_x[b * 64 + h] * fc2w[((size_t)n * 64 + h) * 3 + o];
        }
        s_part[hc * 24 + b * 3 + o] = acc;
    } else if (tid < 320) {
        const int q = tid - 192;
        const int b = q >> 4, which = (q >> 3) & 1, dc = q & 7;
        float s = 0.f;
        const int base = 64 + which * 64 + dc * 8;
        #pragma unroll
        for (int i = 0; i < 8; i++) {
            const float v = s_in[(base + i) * 12 + b];
            s += v * v;
        }
        s_part[256 + (b * 2 + which) * 8 + dc] = s;
    }
    __syncthreads();

    // ---- final fc2 reduce (24 threads) + norm reduce (16 threads) ----
    if (tid < 24) {
        float acc = fc2b[(size_t)n * 3 + tid];
        #pragma unroll
        for (int hc = 0; hc < 8; hc++) acc += s_part[hc * 24 + tid];
        s_o[tid] = acc;
    } else if (tid >= 32 && tid < 48) {
        const int q = tid - 32;
        float s = 0.f;
        #pragma unroll
        for (int i = 0; i < 8; i++) s += s_part[256 + q * 8 + i];
        s_norm[q] = fmaxf(sqrtf(s), 1e-8f);
    }
    __syncthreads();

    // ---- finalize eff_* and init state ----
    {
        const int b = tid >> 6, d = tid & 63;
        const float mod_lr = sigf(mll[0]);
        const float gp = tanhfast(s_o[b * 3 + 0]);
        const float gk = tanhfast(s_o[b * 3 + 1]);
        const float dm = s_o[b * 3 + 2];
        const float tpv = s_in[(64 + d) * 12 + b];
        const float tkv = s_in[(128 + d) * 12 + b];
        const size_t off = ((size_t)b * NN + n) * DD + d;
        g_ep[off] = prim[(size_t)n * DD + d] + mod_lr * gp * (tpv / s_norm[b * 2 + 0]);
        g_ek[off] = keyp[(size_t)n * DD + d] + mod_lr * gk * (tkv / s_norm[b * 2 + 1]);
        g_h [off] = s_in[d * 12 + b];
        g_pmh[0][off] = __float2half_rn(pm_in[off]);
        if (d == 0) g_ed[(size_t)b * NN + n] = sigf(dlog[n] + dm);
    }
}

// =============================================================================
// Kernel B: one scan update.  R8 pipeline-8 shape, but the weighted-branch
// accumulate path is now pure half2 (HMUL2 premul, HFMA2 accumulate, half2 w
// broadcast) — messages & bw are already fp16, so this removes all fp32
// conversions/packs from that path (~25% of the issue stream).  The SIM path
// (sigmoid input) stays fully fp32.  Final pm/out tanh stays precise.
// R10 lesson: issue-bound — occupancy doesn't help.  R4: don't cap regs to 48.
// =============================================================================
__global__ void __launch_bounds__(256, 4) stepk(
    int parity, int t0,
    const float* __restrict__ cc, const float* __restrict__ bw,
    const float* __restrict__ gw, const int* __restrict__ conn,
    float* __restrict__ out)
{
    __shared__ __half2 s_bwh[1024];   // [k][d/2]  fp16 branch weights
    __shared__ float   s_gw[256];     // [nb][d]   fp32 group weights
    __shared__ int     s_idx[32];

    const int n   = blockIdx.x;
    const int tid = threadIdx.x;
    const int b   = tid >> 5;
    const int l   = tid & 31;

    const __half* pm_in  = g_pmh[parity];
    __half*       pm_out = g_pmh[parity ^ 1];

    #pragma unroll
    for (int i = 0; i < 4; i++) {
        const int idx = tid + 256 * i;
        const float2 v = *(const float2*)&bw[(size_t)n * 2048 + 2 * idx];
        s_bwh[idx] = __floats2half2_rn(v.x, v.y);
    }
    s_gw[tid] = gw[(size_t)n * 256 + tid];
    if (tid < 32) s_idx[tid] = conn[(size_t)n * KK + tid];

    const size_t off = ((size_t)b * NN + n) * DD;
    const float2 key = *(const float2*)&g_ek[off + 2 * l];
    __syncthreads();

    const __half2* pmb = (const __half2*)(pm_in + (size_t)b * NN * DD);
    __half2 accp[4];

    __half2 m[8];
    #pragma unroll
    for (int kk = 0; kk < 8; kk++)
        m[kk] = __ldg(&pmb[s_idx[kk] * 32 + l]);

    #pragma unroll
    for (int c = 0; c < 4; c++) {
        // ---- phase 1: fp32 sim partials + half2 premul t = m*bw ----
        float v[8];
        __half2 t[8];
        #pragma unroll
        for (int kk = 0; kk < 8; kk++) {
            const float2 mf = __half22float2(m[kk]);
            v[kk] = key.x * mf.x + key.y * mf.y;
            t[kk] = __hmul2(m[kk], s_bwh[(c * 8 + kk) * 32 + l]);
        }

        // ---- phase 2: prefetch next chunk (overlaps reduce + accumulate) ----
        if (c < 3) {
            #pragma unroll
            for (int kk = 0; kk < 8; kk++)
                m[kk] = __ldg(&pmb[s_idx[(c + 1) * 8 + kk] * 32 + l]);
        }

        // ---- phase 3: fp32 butterfly multi-reduce -> sigmoid ----
        const float w = sigt(multireduce8(v, l));
        const __half2 w2 = __float2half2_rn(w);

        // ---- phase 4: half2 accumulate (chunk c == branch c) ----
        __half2 a = __float2half2_rn(0.f);
        #pragma unroll
        for (int kk = 0; kk < 8; kk++) {
            const __half2 wk2 = __shfl_sync(0xffffffffu, w2, kk << 2);
            a = __hfma2(t[kk], wk2, a);
        }
        accp[c] = a;
    }

    // ---- branch tanh (HW) -> group sum -> group tanh (HW, damped by 0.5) ----
    float r0 = 0.f, r1 = 0.f;
    #pragma unroll
    for (int nb = 0; nb < 4; nb++) {
        const float2 av  = __half22float2(accp[nb]);
        const float2 gwv = *(const float2*)&s_gw[nb * 64 + 2 * l];
        r0 += tanha(av.x) * gwv.x;
        r1 += tanha(av.y) * gwv.y;
    }
    r0 = tanha(r0);
    r1 = tanha(r1);

    if (n < C_) {   // cc injection on first C neurons
        const float2 ccv = *(const float2*)&cc[(((size_t)b * T_ + t0) * C_ + n) * DD + 2 * l];
        r0 += ccv.x;
        r1 += ccv.y;
    }

    // ---- h / message update (fp32; output-facing tanh stays precise) ----
    const float ed = g_ed[(size_t)b * NN + n];
    const float2 h = *(const float2*)&g_h[off + 2 * l];
    const float nh0 = ed * h.x + (1.f - ed) * r0;
    const float nh1 = ed * h.y + (1.f - ed) * r1;
    *(float2*)&g_h[off + 2 * l] = make_float2(nh0, nh1);
    const float2 ep = *(const float2*)&g_ep[off + 2 * l];
    const float p0 = tanhfast(nh0 * ep.x);
    const float p1 = tanhfast(nh1 * ep.y);
    *((__half2*)(pm_out + off) + l) = __floats2half2_rn(p0, p1);

    if (n < C_) {   // emit the 4 timesteps this update covers (fp32 output)
        #pragma unroll
        for (int tt = 0; tt < 4; tt++) {
            const size_t oo = (((size_t)b * T_ + t0 + tt) * C_ + n) * DD + 2 * l;
            *(float2*)&out[oo] = make_float2(p0, p1);
        }
    }
}

// =============================================================================
extern "C" void kernel_launch(void* const* d_in, const int* in_sizes, int n_in,
                              void* d_out, int out_size)
{
    const float* cc    = (const float*)d_in[0];
    const float* h_in  = (const float*)d_in[1];
    const float* pm_in = (const float*)d_in[2];
    const float* tp    = (const float*)d_in[3];
    const float* tk    = (const float*)d_in[4];
    const float* prim  = (const float*)d_in[5];
    const float* keyp  = (const float*)d_in[6];
    const float* dlog  = (const float*)d_in[7];
    const float* bw    = (const float*)d_in[8];
    const float* gw    = (const float*)d_in[9];
    const float* fc1w  = (const float*)d_in[10];
    const float* fc1b  = (const float*)d_in[11];
    const float* fc2w  = (const float*)d_in[12];
    const float* fc2b  = (const float*)d_in[13];
    const float* mll   = (const float*)d_in[14];
    const int*   conn  = (const int*)d_in[15];
    float* out = (float*)d_out;

    modk<<<NN, 512>>>(h_in, pm_in, tp, tk, prim, keyp, dlog,
                      fc1w, fc1b, fc2w, fc2b, mll);

    // stride = 4 (fixed by setup): updates at t = 0,4,...,28; output replicated x4
    for (int u = 0; u < 8; u++) {
        stepk<<<NN, 256>>>(u & 1, 4 * u, cc, bw, gw, conn, out);
    }
}